// round 12
// baseline (speedup 1.0000x reference)
#include <cuda_runtime.h>
#include <cstdint>

// FMLayer: out[b, p] = wdot[p] * x[b, j1(p)] * x[b, j2(p)]
//   N_FEATURES = 512, K = 4, BATCH = 1024, P = 130816 (upper triangle, row-major by j1)
// DRAM-write-bound: 535.8 MB out per launch (~67 us floor @ 8 TB/s).
// R11 lesson: .wb regressed; __stcs restored. This round: persistent blocks
// (4 x SM_count) looping over the 4096 tiles -> single wave, no inter-wave
// transitions, <=1-tile imbalance. Hot loop body is byte-identical to R10.

#define NF    512
#define BATCH 1024
#define NPAIR 130816              // 512*511/2
#define NQ4   (NPAIR / 4)         // 32704 float4 slots per batch row
#define BT    4                   // batch rows per block
#define TPB   512                 // threads per block
#define NCHUNK 16                 // pair chunks of 2048 float4
#define NTILE (NCHUNK * (BATCH / BT))   // 4096 tiles

// Scratch (allocation-free rule: __device__ globals)
__device__ __align__(16) float g_wdot[NPAIR];
__device__ __align__(16) int   g_jidx[NPAIR];   // (j1<<16)|j2 per pair (slow path)
__device__ __align__(16) int   g_meta[NQ4];     // (j1<<16)|j2start, or -1 if row-crossing

__device__ __forceinline__ int tri_off(int j) {
    return (NF - 1) * j - ((j * (j - 1)) >> 1);
}

// largest j1 with tri_off(j1) <= p ; j1 in [0,510] -> 9 branch-free steps, int-only
__device__ __forceinline__ int find_row(int p) {
    int lo = 0, hi = NF - 2;
    #pragma unroll
    for (int it = 0; it < 9; it++) {
        int mid = (lo + hi + 1) >> 1;
        if (tri_off(mid) <= p) lo = mid; else hi = mid - 1;
    }
    return lo;
}

// One thread per float4-slot q: recover (j1,j2) for p=4q, walk 4 pairs
// incrementally (exact row-crossing handling), emit wdot4/jidx4/meta.
__global__ void __launch_bounds__(256) fm_setup_kernel(const float* __restrict__ w) {
    int q = blockIdx.x * blockDim.x + threadIdx.x;
    if (q >= NQ4) return;

    int p  = 4 * q;
    int j1 = find_row(p);
    int j2 = p - tri_off(j1) + j1 + 1;

    const float4* w4 = reinterpret_cast<const float4*>(w);  // 8 KB, L1-resident
    float4 wa = __ldg(&w4[j1]);

    int   r1 = j1, r2 = j2;
    int   jj[4];
    float wdv[4];
    #pragma unroll
    for (int e = 0; e < 4; e++) {
        if (r2 >= NF) { r1++; r2 = r1 + 1; wa = __ldg(&w4[r1]); }
        float4 wb = __ldg(&w4[r2]);
        wdv[e] = wa.x * wb.x + wa.y * wb.y + wa.z * wb.z + wa.w * wb.w;
        jj[e]  = (r1 << 16) | r2;
        r2++;
    }

    reinterpret_cast<float4*>(g_wdot)[q] = make_float4(wdv[0], wdv[1], wdv[2], wdv[3]);
    reinterpret_cast<int4*>(g_jidx)[q]   = make_int4(jj[0], jj[1], jj[2], jj[3]);
    g_meta[q] = ((jj[0] >> 16) == (jj[3] >> 16)) ? jj[0] : -1;
}

// Persistent: each block loops over tiles (chunk, ygroup) with stride gridDim.x.
// Per tile: barrier, refill smem (4 x rows, 4 shifted copies), barrier, stream.
// Inner streaming body identical to R10 (with __stcs).
__global__ void __launch_bounds__(TPB, 4) fm_main_kernel(
    const float* __restrict__ x, float* __restrict__ out)
{
    __shared__ float xs[BT][4][NF];   // xs[b][a][i] = x_row_b[a + i]; 32 KB

    // wait for fm_setup_kernel (PDL): tables valid beyond this point
    cudaGridDependencySynchronize();

    const int4*   jid4 = reinterpret_cast<const int4*>(g_jidx);
    const float4* wd4  = reinterpret_cast<const float4*>(g_wdot);

    for (int t = blockIdx.x; t < NTILE; t += gridDim.x) {
        const int chunk  = t & (NCHUNK - 1);
        const int b0     = (t >> 4) * BT;      // t / NCHUNK * BT

        __syncthreads();   // prior tile's reads of xs complete before refill

        for (int i = threadIdx.x; i < BT * NF; i += TPB) {
            int bb = i >> 9;              // / NF
            int j  = i & (NF - 1);
            float v = x[(size_t)(b0 + bb) * NF + j];
            #pragma unroll
            for (int a = 0; a < 4; a++)
                if (j >= a) xs[bb][a][j - a] = v;
        }
        __syncthreads();

        float4* ob0 = reinterpret_cast<float4*>(out) + (size_t)b0 * NQ4;
        const int qbase = chunk * (TPB * 4) + threadIdx.x;

        #pragma unroll
        for (int u = 0; u < 4; u++) {
            int q = qbase + u * TPB;
            if (q >= NQ4) continue;       // only last chunk partially masked
            int    mu = __ldg(&g_meta[q]);
            float4 wv = __ldg(&wd4[q]);

            if (mu >= 0) {
                // fast path: all 4 pairs share j1, j2..j2+3 contiguous
                int j1  = mu >> 16;
                int j2s = mu & 0xffff;
                int a   = j2s & 3;
                int idx = (j2s - a) >> 2;
                #pragma unroll
                for (int bb = 0; bb < BT; bb++) {
                    float  s  = xs[bb][0][j1];
                    float4 xv = reinterpret_cast<const float4*>(xs[bb][a])[idx];
                    float4 r;
                    r.x = s * wv.x * xv.x;
                    r.y = s * wv.y * xv.y;
                    r.z = s * wv.z * xv.z;
                    r.w = s * wv.w * xv.w;
                    __stcs(&ob0[(size_t)bb * NQ4 + q], r);
                }
            } else {
                // slow path (1.6% of slots): row-crossing, per-element gather
                int4 j = __ldg(&jid4[q]);
                #pragma unroll
                for (int bb = 0; bb < BT; bb++) {
                    const float* xr = xs[bb][0];
                    float4 r;
                    r.x = wv.x * xr[j.x >> 16] * xr[j.x & 0xffff];
                    r.y = wv.y * xr[j.y >> 16] * xr[j.y & 0xffff];
                    r.z = wv.z * xr[j.z >> 16] * xr[j.z & 0xffff];
                    r.w = wv.w * xr[j.w >> 16] * xr[j.w & 0xffff];
                    __stcs(&ob0[(size_t)bb * NQ4 + q], r);
                }
            }
        }
    }
}

extern "C" void kernel_launch(void* const* d_in, const int* in_sizes, int n_in,
                              void* d_out, int out_size)
{
    const float* x = (const float*)d_in[0];   // [1024, 512]
    const float* w = (const float*)d_in[1];   // [512, 4]
    float* out = (float*)d_out;               // [1024, 130816]
    (void)in_sizes; (void)n_in; (void)out_size;

    // capture-time host query (baked into the graph; no per-replay cost)
    int dev = 0, nsm = 148;
    cudaGetDevice(&dev);
    cudaDeviceGetAttribute(&nsm, cudaDevAttrMultiProcessorCount, dev);
    int nblocks = 4 * nsm;                    // 1 resident wave
    if (nblocks > NTILE) nblocks = NTILE;

    fm_setup_kernel<<<(NQ4 + 255) / 256, 256>>>(w);

    // PDL launch: persistent main kernel starts early; grid-syncs before tables.
    cudaLaunchConfig_t cfg = {};
    cfg.gridDim  = dim3(nblocks, 1, 1);
    cfg.blockDim = dim3(TPB, 1, 1);
    cfg.dynamicSmemBytes = 0;
    cfg.stream = 0;
    cudaLaunchAttribute attrs[1];
    attrs[0].id = cudaLaunchAttributeProgrammaticStreamSerialization;
    attrs[0].val.programmaticStreamSerializationAllowed = 1;
    cfg.attrs = attrs;
    cfg.numAttrs = 1;
    cudaLaunchKernelEx(&cfg, fm_main_kernel, x, out);
}

// round 13
// speedup vs baseline: 1.1185x; 1.1185x over previous
#include <cuda_runtime.h>
#include <cstdint>

// FMLayer: out[b, p] = wdot[p] * x[b, j1(p)] * x[b, j2(p)]
//   N_FEATURES = 512, K = 4, BATCH = 1024, P = 130816 (upper triangle, row-major by j1)
// DRAM-write-bound: 535.8 MB out per launch (~67 us floor @ 8 TB/s).
// R12 lesson: persistent blocks serialize fill with streaming -> regressed.
// Exact R10 structure restored. Single change this round: __stwt stores
// (write-through; no L2 dirty-line bookkeeping for the one-way stream).
// Policy map so far: .cs=82.8us, .wb=86.1us, .wt=this round.

#define NF    512
#define BATCH 1024
#define NPAIR 130816              // 512*511/2
#define NQ4   (NPAIR / 4)         // 32704 float4 slots per batch row
#define BT    4                   // batch rows per block
#define TPB   512                 // threads per block

// Scratch (allocation-free rule: __device__ globals)
__device__ __align__(16) float g_wdot[NPAIR];
__device__ __align__(16) int   g_jidx[NPAIR];   // (j1<<16)|j2 per pair (slow path)
__device__ __align__(16) int   g_meta[NQ4];     // (j1<<16)|j2start, or -1 if row-crossing

__device__ __forceinline__ int tri_off(int j) {
    return (NF - 1) * j - ((j * (j - 1)) >> 1);
}

// largest j1 with tri_off(j1) <= p ; j1 in [0,510] -> 9 branch-free steps, int-only
__device__ __forceinline__ int find_row(int p) {
    int lo = 0, hi = NF - 2;
    #pragma unroll
    for (int it = 0; it < 9; it++) {
        int mid = (lo + hi + 1) >> 1;
        if (tri_off(mid) <= p) lo = mid; else hi = mid - 1;
    }
    return lo;
}

// One thread per float4-slot q: recover (j1,j2) for p=4q, walk 4 pairs
// incrementally (exact row-crossing handling), emit wdot4/jidx4/meta.
__global__ void __launch_bounds__(256) fm_setup_kernel(const float* __restrict__ w) {
    int q = blockIdx.x * blockDim.x + threadIdx.x;
    if (q >= NQ4) return;

    int p  = 4 * q;
    int j1 = find_row(p);
    int j2 = p - tri_off(j1) + j1 + 1;

    const float4* w4 = reinterpret_cast<const float4*>(w);  // 8 KB, L1-resident
    float4 wa = __ldg(&w4[j1]);

    int   r1 = j1, r2 = j2;
    int   jj[4];
    float wdv[4];
    #pragma unroll
    for (int e = 0; e < 4; e++) {
        if (r2 >= NF) { r1++; r2 = r1 + 1; wa = __ldg(&w4[r1]); }
        float4 wb = __ldg(&w4[r2]);
        wdv[e] = wa.x * wb.x + wa.y * wb.y + wa.z * wb.z + wa.w * wb.w;
        jj[e]  = (r1 << 16) | r2;
        r2++;
    }

    reinterpret_cast<float4*>(g_wdot)[q] = make_float4(wdv[0], wdv[1], wdv[2], wdv[3]);
    reinterpret_cast<int4*>(g_jidx)[q]   = make_int4(jj[0], jj[1], jj[2], jj[3]);
    g_meta[q] = ((jj[0] >> 16) == (jj[3] >> 16)) ? jj[0] : -1;
}

// Block = (chunk of 2048 float4 slots) x (BT=4 batch rows). 512 threads, 4 slots each.
// R10-proven body + PDL: fill smem (table-independent), grid-sync, then stream.
__global__ void __launch_bounds__(TPB, 4) fm_main_kernel(
    const float* __restrict__ x, float* __restrict__ out)
{
    __shared__ float xs[BT][4][NF];   // xs[b][a][i] = x_row_b[a + i]; 32 KB

    const int b0 = blockIdx.y * BT;

    for (int i = threadIdx.x; i < BT * NF; i += TPB) {
        int bb = i >> 9;              // / NF
        int j  = i & (NF - 1);
        float v = x[(size_t)(b0 + bb) * NF + j];
        #pragma unroll
        for (int a = 0; a < 4; a++)
            if (j >= a) xs[bb][a][j - a] = v;
    }
    __syncthreads();

    // wait for fm_setup_kernel (PDL): tables valid beyond this point
    cudaGridDependencySynchronize();

    const int4*   jid4 = reinterpret_cast<const int4*>(g_jidx);
    const float4* wd4  = reinterpret_cast<const float4*>(g_wdot);
    float4* ob0 = reinterpret_cast<float4*>(out) + (size_t)b0 * NQ4;

    const int qbase = blockIdx.x * (TPB * 4) + threadIdx.x;

    #pragma unroll
    for (int u = 0; u < 4; u++) {
        int q = qbase + u * TPB;
        if (q >= NQ4) continue;       // only last chunk partially masked
        int    mu = __ldg(&g_meta[q]);
        float4 wv = __ldg(&wd4[q]);

        if (mu >= 0) {
            // fast path: all 4 pairs share j1, j2..j2+3 contiguous
            int j1  = mu >> 16;
            int j2s = mu & 0xffff;
            int a   = j2s & 3;
            int idx = (j2s - a) >> 2;
            #pragma unroll
            for (int bb = 0; bb < BT; bb++) {
                float  s  = xs[bb][0][j1];
                float4 xv = reinterpret_cast<const float4*>(xs[bb][a])[idx];
                float4 r;
                r.x = s * wv.x * xv.x;
                r.y = s * wv.y * xv.y;
                r.z = s * wv.z * xv.z;
                r.w = s * wv.w * xv.w;
                __stwt(&ob0[(size_t)bb * NQ4 + q], r);   // write-through
            }
        } else {
            // slow path (1.6% of slots): row-crossing, per-element gather
            int4 j = __ldg(&jid4[q]);
            #pragma unroll
            for (int bb = 0; bb < BT; bb++) {
                const float* xr = xs[bb][0];
                float4 r;
                r.x = wv.x * xr[j.x >> 16] * xr[j.x & 0xffff];
                r.y = wv.y * xr[j.y >> 16] * xr[j.y & 0xffff];
                r.z = wv.z * xr[j.z >> 16] * xr[j.z & 0xffff];
                r.w = wv.w * xr[j.w >> 16] * xr[j.w & 0xffff];
                __stwt(&ob0[(size_t)bb * NQ4 + q], r);   // write-through
            }
        }
    }
}

extern "C" void kernel_launch(void* const* d_in, const int* in_sizes, int n_in,
                              void* d_out, int out_size)
{
    const float* x = (const float*)d_in[0];   // [1024, 512]
    const float* w = (const float*)d_in[1];   // [512, 4]
    float* out = (float*)d_out;               // [1024, 130816]
    (void)in_sizes; (void)n_in; (void)out_size;

    fm_setup_kernel<<<(NQ4 + 255) / 256, 256>>>(w);

    // PDL launch: main kernel's blocks may start before setup completes;
    // they grid-sync before touching the tables.
    dim3 grid(16, BATCH / BT);   // 16 * 2048 f4 = 32768 >= 32704 (guarded)

    cudaLaunchConfig_t cfg = {};
    cfg.gridDim  = grid;
    cfg.blockDim = dim3(TPB, 1, 1);
    cfg.dynamicSmemBytes = 0;
    cfg.stream = 0;
    cudaLaunchAttribute attrs[1];
    attrs[0].id = cudaLaunchAttributeProgrammaticStreamSerialization;
    attrs[0].val.programmaticStreamSerializationAllowed = 1;
    cfg.attrs = attrs;
    cfg.numAttrs = 1;
    cudaLaunchKernelEx(&cfg, fm_main_kernel, x, out);
}

// round 14
// speedup vs baseline: 1.1724x; 1.0481x over previous
#include <cuda_runtime.h>
#include <cstdint>

// FMLayer: out[b, p] = wdot[p] * x[b, j1(p)] * x[b, j2(p)]
//   N_FEATURES = 512, K = 4, BATCH = 1024, P = 130816 (upper triangle, row-major by j1)
// DRAM-write-bound: 535.8 MB out per launch (~67 us floor @ 8 TB/s).
//
// FINAL (converged) configuration — re-confirmation of the R10 optimum:
//   * TPB=512, BT=4, 4 blocks/SM (32 KB smem), slot-outer/batch-inner loop
//   * 4 shifted smem copies of each x row -> aligned LDS.128 for x[j2..j2+3]
//   * per-slot meta/wdot via in-loop __ldg (L2-resident tables)
//   * __stcs streaming stores (policy axis mapped: .cs 82.8 < .wb 86.1 < .wt 86.4)
//   * setup kernel hidden under main's fill phase via PDL
// All structural perturbations tested (BT=2/8, TPB=1024, hoisted loads,
// persistent blocks) regressed; this shape is the measured optimum.

#define NF    512
#define BATCH 1024
#define NPAIR 130816              // 512*511/2
#define NQ4   (NPAIR / 4)         // 32704 float4 slots per batch row
#define BT    4                   // batch rows per block
#define TPB   512                 // threads per block

// Scratch (allocation-free rule: __device__ globals)
__device__ __align__(16) float g_wdot[NPAIR];
__device__ __align__(16) int   g_jidx[NPAIR];   // (j1<<16)|j2 per pair (slow path)
__device__ __align__(16) int   g_meta[NQ4];     // (j1<<16)|j2start, or -1 if row-crossing

__device__ __forceinline__ int tri_off(int j) {
    return (NF - 1) * j - ((j * (j - 1)) >> 1);
}

// largest j1 with tri_off(j1) <= p ; j1 in [0,510] -> 9 branch-free steps, int-only
__device__ __forceinline__ int find_row(int p) {
    int lo = 0, hi = NF - 2;
    #pragma unroll
    for (int it = 0; it < 9; it++) {
        int mid = (lo + hi + 1) >> 1;
        if (tri_off(mid) <= p) lo = mid; else hi = mid - 1;
    }
    return lo;
}

// One thread per float4-slot q: recover (j1,j2) for p=4q, walk 4 pairs
// incrementally (exact row-crossing handling), emit wdot4/jidx4/meta.
__global__ void __launch_bounds__(256) fm_setup_kernel(const float* __restrict__ w) {
    int q = blockIdx.x * blockDim.x + threadIdx.x;
    if (q >= NQ4) return;

    int p  = 4 * q;
    int j1 = find_row(p);
    int j2 = p - tri_off(j1) + j1 + 1;

    const float4* w4 = reinterpret_cast<const float4*>(w);  // 8 KB, L1-resident
    float4 wa = __ldg(&w4[j1]);

    int   r1 = j1, r2 = j2;
    int   jj[4];
    float wdv[4];
    #pragma unroll
    for (int e = 0; e < 4; e++) {
        if (r2 >= NF) { r1++; r2 = r1 + 1; wa = __ldg(&w4[r1]); }
        float4 wb = __ldg(&w4[r2]);
        wdv[e] = wa.x * wb.x + wa.y * wb.y + wa.z * wb.z + wa.w * wb.w;
        jj[e]  = (r1 << 16) | r2;
        r2++;
    }

    reinterpret_cast<float4*>(g_wdot)[q] = make_float4(wdv[0], wdv[1], wdv[2], wdv[3]);
    reinterpret_cast<int4*>(g_jidx)[q]   = make_int4(jj[0], jj[1], jj[2], jj[3]);
    g_meta[q] = ((jj[0] >> 16) == (jj[3] >> 16)) ? jj[0] : -1;
}

// Block = (chunk of 2048 float4 slots) x (BT=4 batch rows). 512 threads, 4 slots each.
// PDL: fill smem (table-independent), grid-sync, then stream.
__global__ void __launch_bounds__(TPB, 4) fm_main_kernel(
    const float* __restrict__ x, float* __restrict__ out)
{
    __shared__ float xs[BT][4][NF];   // xs[b][a][i] = x_row_b[a + i]; 32 KB

    const int b0 = blockIdx.y * BT;

    for (int i = threadIdx.x; i < BT * NF; i += TPB) {
        int bb = i >> 9;              // / NF
        int j  = i & (NF - 1);
        float v = x[(size_t)(b0 + bb) * NF + j];
        #pragma unroll
        for (int a = 0; a < 4; a++)
            if (j >= a) xs[bb][a][j - a] = v;
    }
    __syncthreads();

    // wait for fm_setup_kernel (PDL): tables valid beyond this point
    cudaGridDependencySynchronize();

    const int4*   jid4 = reinterpret_cast<const int4*>(g_jidx);
    const float4* wd4  = reinterpret_cast<const float4*>(g_wdot);
    float4* ob0 = reinterpret_cast<float4*>(out) + (size_t)b0 * NQ4;

    const int qbase = blockIdx.x * (TPB * 4) + threadIdx.x;

    #pragma unroll
    for (int u = 0; u < 4; u++) {
        int q = qbase + u * TPB;
        if (q >= NQ4) continue;       // only last chunk partially masked
        int    mu = __ldg(&g_meta[q]);
        float4 wv = __ldg(&wd4[q]);

        if (mu >= 0) {
            // fast path: all 4 pairs share j1, j2..j2+3 contiguous
            int j1  = mu >> 16;
            int j2s = mu & 0xffff;
            int a   = j2s & 3;
            int idx = (j2s - a) >> 2;
            #pragma unroll
            for (int bb = 0; bb < BT; bb++) {
                float  s  = xs[bb][0][j1];
                float4 xv = reinterpret_cast<const float4*>(xs[bb][a])[idx];
                float4 r;
                r.x = s * wv.x * xv.x;
                r.y = s * wv.y * xv.y;
                r.z = s * wv.z * xv.z;
                r.w = s * wv.w * xv.w;
                __stcs(&ob0[(size_t)bb * NQ4 + q], r);   // evict-first streaming store
            }
        } else {
            // slow path (1.6% of slots): row-crossing, per-element gather
            int4 j = __ldg(&jid4[q]);
            #pragma unroll
            for (int bb = 0; bb < BT; bb++) {
                const float* xr = xs[bb][0];
                float4 r;
                r.x = wv.x * xr[j.x >> 16] * xr[j.x & 0xffff];
                r.y = wv.y * xr[j.y >> 16] * xr[j.y & 0xffff];
                r.z = wv.z * xr[j.z >> 16] * xr[j.z & 0xffff];
                r.w = wv.w * xr[j.w >> 16] * xr[j.w & 0xffff];
                __stcs(&ob0[(size_t)bb * NQ4 + q], r);   // evict-first streaming store
            }
        }
    }
}

extern "C" void kernel_launch(void* const* d_in, const int* in_sizes, int n_in,
                              void* d_out, int out_size)
{
    const float* x = (const float*)d_in[0];   // [1024, 512]
    const float* w = (const float*)d_in[1];   // [512, 4]
    float* out = (float*)d_out;               // [1024, 130816]
    (void)in_sizes; (void)n_in; (void)out_size;

    fm_setup_kernel<<<(NQ4 + 255) / 256, 256>>>(w);

    // PDL launch: main kernel's blocks may start before setup completes;
    // they grid-sync before touching the tables.
    dim3 grid(16, BATCH / BT);   // 16 * 2048 f4 = 32768 >= 32704 (guarded)

    cudaLaunchConfig_t cfg = {};
    cfg.gridDim  = grid;
    cfg.blockDim = dim3(TPB, 1, 1);
    cfg.dynamicSmemBytes = 0;
    cfg.stream = 0;
    cudaLaunchAttribute attrs[1];
    attrs[0].id = cudaLaunchAttributeProgrammaticStreamSerialization;
    attrs[0].val.programmaticStreamSerializationAllowed = 1;
    cfg.attrs = attrs;
    cfg.numAttrs = 1;
    cudaLaunchKernelEx(&cfg, fm_main_kernel, x, out);
}